// round 16
// baseline (speedup 1.0000x reference)
#include <cuda_runtime.h>

#define NB 16
#define TQ 256
#define TK 256
#define DD 256
#define FF 36
#define HH 8
#define DK 32
#define SFD 6

// Scratch (allocation-free rule: __device__ globals)
__device__ float g_Q[NB*TQ*DD];        // [b][q][h*DK+j]
__device__ float g_K[NB*TK*DD];        // [b][k][h*DK+j]
#define ND_SPLIT ((size_t)NB*TQ*FF*HH)
__device__ float2 g_ND[2*NB*TQ*FF*HH]; // [ksplit][b][q][f][h] = (num, den)

// ---------------------------------------------------------------------------
// Packed fp32x2 helpers (sm_103a: FFMA2 via PTX only)
// ---------------------------------------------------------------------------
__device__ __forceinline__ float2 fma2(float2 a, float2 b, float2 c) {
    float2 d;
    asm("fma.rn.f32x2 %0, %1, %2, %3;"
        : "=l"(reinterpret_cast<unsigned long long&>(d))
        : "l"(reinterpret_cast<unsigned long long&>(a)),
          "l"(reinterpret_cast<unsigned long long&>(b)),
          "l"(reinterpret_cast<unsigned long long&>(c)));
    return d;
}
__device__ __forceinline__ float2 dup2(float s) { return make_float2(s, s); }
__device__ __forceinline__ float2 tanh2(float2 a) {
    float2 r;
    asm("tanh.approx.f32 %0, %1;" : "=f"(r.x) : "f"(a.x));
    asm("tanh.approx.f32 %0, %1;" : "=f"(r.y) : "f"(a.y));
    return r;
}

// ---------------------------------------------------------------------------
// Kernel 1: register-tiled SGEMM, tile 128x32 (was 128x64).
// Grid (32,8,2)=512 blocks -> ~3.4 blocks/SM, ~26 warps/SM (2x R15).
// Thread owns 8 rows x 2 cols; per kk: 2 LDS.128 + 1 LDS.64 + 8 FFMA2.
// ---------------------------------------------------------------------------
#define PM 128
#define PN 32
#define PKT 16

__global__ void __launch_bounds__(256) proj_kernel(
        const float* __restrict__ query, const float* __restrict__ key,
        const float* __restrict__ Wq,    const float* __restrict__ Wk) {
    __shared__ __align__(16) float As[PKT][PM + 4];   // [kk][n] plain
    __shared__ __align__(16) float Bs[PKT][PN + 4];   // [kk][c]

    int n0 = blockIdx.x * PM;
    int c0 = blockIdx.y * PN;
    int which = blockIdx.z;
    const float* x = which ? key : query;
    const float* W = which ? Wk : Wq;

    int t  = threadIdx.x;
    int tm = t >> 4;          // rows 4tm..4tm+3 and +64
    int tn = t & 15;          // cols 2tn..2tn+1

    // fill-index precompute
    int fa_n  = t >> 1;                 // A fill: row 0..127, 1 float4
    int fa_k  = (t & 1) * 8;            //   k offsets 0..7 / 8..15
    // B fill: 16kk x 32c = 512 floats = 128 float4; threads t<128, 1 each
    int fb_kk = t >> 3;                 // kk row 0..15
    int fb_c  = (t & 7) * 4;            //   col offset (1 float4)
    int fb_h  = c0 >> 5;                // c0 multiple of 32 -> single head
    // W element: W[fb_h][d][ (c0&31) + fb_c + lane ], row d = kt + fb_kk

    float2 acc[8];
#pragma unroll
    for (int r = 0; r < 8; ++r) acc[r] = make_float2(0.f, 0.f);

    // ---- prefetch tile 0 into registers
    float4 pa0, pa1, pb;
    {
        const float* xr = x + (size_t)(n0 + fa_n)*DD + fa_k;
        pa0 = *(const float4*)(xr);
        pa1 = *(const float4*)(xr + 4);
        pb  = (t < 128)
            ? *(const float4*)(W + ((size_t)fb_h*DD + fb_kk)*DK + (c0 & 31) + fb_c)
            : make_float4(0.f, 0.f, 0.f, 0.f);
    }

#pragma unroll 1
    for (int kt = 0; kt < DD; kt += PKT) {
        // ---- store prefetched regs to smem
        As[fa_k+0][fa_n] = pa0.x;
        As[fa_k+1][fa_n] = pa0.y;
        As[fa_k+2][fa_n] = pa0.z;
        As[fa_k+3][fa_n] = pa0.w;
        As[fa_k+4][fa_n] = pa1.x;
        As[fa_k+5][fa_n] = pa1.y;
        As[fa_k+6][fa_n] = pa1.z;
        As[fa_k+7][fa_n] = pa1.w;
        if (t < 128)
            *(float4*)(&Bs[fb_kk][fb_c]) = pb;
        __syncthreads();

        // ---- prefetch next tile (overlaps compute)
        if (kt + PKT < DD) {
            const float* xr = x + (size_t)(n0 + fa_n)*DD + kt + PKT + fa_k;
            pa0 = *(const float4*)(xr);
            pa1 = *(const float4*)(xr + 4);
            if (t < 128)
                pb = *(const float4*)(W + ((size_t)fb_h*DD + kt + PKT + fb_kk)*DK
                                      + (c0 & 31) + fb_c);
        }

        // ---- compute: per kk, 2 LDS.128 + 1 LDS.64 + 8 reg-dups, 8 FFMA2
#pragma unroll
        for (int kk = 0; kk < PKT; ++kk) {
            float4 alo = *(const float4*)&As[kk][4*tm];        // rows 4tm..+3
            float4 ahi = *(const float4*)&As[kk][4*tm + 64];   // rows +64
            float2 bv  = *(const float2*)&Bs[kk][2*tn];
            float2 a[8];
            a[0] = dup2(alo.x); a[1] = dup2(alo.y);
            a[2] = dup2(alo.z); a[3] = dup2(alo.w);
            a[4] = dup2(ahi.x); a[5] = dup2(ahi.y);
            a[6] = dup2(ahi.z); a[7] = dup2(ahi.w);
#pragma unroll
            for (int r = 0; r < 8; ++r)
                acc[r] = fma2(a[r], bv, acc[r]);
        }
        __syncthreads();
    }

    // ---- write out: 8 rows x 1 STG.64
    float* out = which ? g_K : g_Q;
#pragma unroll
    for (int r = 0; r < 8; ++r) {
        int n = n0 + 4*tm + (r >> 2)*64 + (r & 3);
        *(float2*)(out + (size_t)n*DD + c0 + 2*tn) = acc[r];
    }
}

// ---------------------------------------------------------------------------
// Kernel 2 (fused score+apply, split-K; exact R15): grid (NB, HH, 8);
// z = qtile*2 + ks. Each block covers k range [ks*128, ks*128+128).
// ---------------------------------------------------------------------------
__global__ void __launch_bounds__(128, 5) fused_attn_kernel(
        const float* __restrict__ value, const float* __restrict__ mask) {
    int b = blockIdx.x, h = blockIdx.y;
    int q0 = (blockIdx.z >> 1) * 64;
    int ks = blockIdx.z & 1;
    int t = threadIdx.x;

    __shared__ __align__(16) float Qst[32][68];     // [j][q]
    __shared__ __align__(16) float Ksd[32][66];     // [kk][2j] dup'd
    __shared__ __align__(16) float Es[32][68];      // [kk][q]
    __shared__ __align__(16) float Cs[32][4][20];   // [kk][fg][(mv,m)x9 + pad]

    for (int i = t; i < 64*32; i += 128) {
        int q = i >> 5, j = i & 31;
        Qst[j][q] = g_Q[(size_t)(b*TQ + q0 + q)*DD + h*DK + j];
    }

    int qg = t >> 2;            // q local = qg*2 + qq
    int fg = t & 3;             // f = fg*9 + i
    int kkA = t & 31;
    int qq4 = t >> 5;           // 16-q chunk

    float2 nd[2][9];
#pragma unroll
    for (int qq = 0; qq < 2; ++qq)
#pragma unroll
        for (int i = 0; i < 9; ++i) nd[qq][i] = make_float2(0.f, 0.f);

    int ktEnd = ks*128 + 128;
#pragma unroll 1
    for (int kt = ks*128; kt < ktEnd; kt += 32) {
        __syncthreads();
#pragma unroll
        for (int r = 0; r < 8; ++r) {
            int i = t + r*128;
            int kk = i >> 5, j = i & 31;
            float kv = g_K[(size_t)(b*TK + kt + kk)*DD + h*DK + j];
            *(float2*)&Ksd[kk][2*j] = make_float2(kv, kv);
        }
        for (int i = t; i < 288; i += 128) {
            int k = i / 9;
            int c4 = (i - k*9) * 4;
            size_t base = (size_t)(b*TK + kt + k)*FF + c4;
            float4 mm = *(const float4*)(mask + base);
            float4 vv = *(const float4*)(value + base);
#pragma unroll
            for (int u = 0; u < 4; ++u) {
                int f = c4 + u;
                int g = f / 9, ii = f - g*9;
                float m = (&mm.x)[u], v = (&vv.x)[u];
                Cs[k][g][2*ii]   = m * v;
                Cs[k][g][2*ii+1] = m;
            }
        }
        __syncthreads();

        // ---- Phase A
        {
            float2 acc2[8];
#pragma unroll
            for (int p = 0; p < 8; ++p) acc2[p] = make_float2(0.f, 0.f);
#pragma unroll
            for (int jc = 0; jc < 4; ++jc) {
                float2 kr2[8];
#pragma unroll
                for (int j = 0; j < 8; ++j)
                    kr2[j] = *(const float2*)&Ksd[kkA][2*(jc*8 + j)];
#pragma unroll
                for (int j = 0; j < 8; ++j) {
                    const float4* qp = (const float4*)&Qst[jc*8 + j][qq4*16];
#pragma unroll
                    for (int c = 0; c < 4; ++c) {
                        float4 qv = qp[c];
                        acc2[2*c]   = fma2(*(const float2*)&qv.x, kr2[j], acc2[2*c]);
                        acc2[2*c+1] = fma2(*(const float2*)&qv.z, kr2[j], acc2[2*c+1]);
                    }
                }
            }
#pragma unroll
            for (int c = 0; c < 4; ++c) {
                float4 ev;
                ev.x = __expf(fminf(acc2[2*c].x,   80.f));
                ev.y = __expf(fminf(acc2[2*c].y,   80.f));
                ev.z = __expf(fminf(acc2[2*c+1].x, 80.f));
                ev.w = __expf(fminf(acc2[2*c+1].y, 80.f));
                *(float4*)&Es[kkA][qq4*16 + 4*c] = ev;
            }
        }
        __syncthreads();

        // ---- Phase B
#pragma unroll 4
        for (int kk = 0; kk < 32; ++kk) {
            float2 e2 = *(const float2*)&Es[kk][qg*2];
            float2 e0 = dup2(e2.x), e1 = dup2(e2.y);
            const float4* cp = (const float4*)&Cs[kk][fg][0];
            float4 c0 = cp[0], c1 = cp[1], c2 = cp[2], c3 = cp[3], c4v = cp[4];
            nd[0][0] = fma2(e0, *(const float2*)&c0.x,  nd[0][0]);
            nd[1][0] = fma2(e1, *(const float2*)&c0.x,  nd[1][0]);
            nd[0][1] = fma2(e0, *(const float2*)&c0.z,  nd[0][1]);
            nd[1][1] = fma2(e1, *(const float2*)&c0.z,  nd[1][1]);
            nd[0][2] = fma2(e0, *(const float2*)&c1.x,  nd[0][2]);
            nd[1][2] = fma2(e1, *(const float2*)&c1.x,  nd[1][2]);
            nd[0][3] = fma2(e0, *(const float2*)&c1.z,  nd[0][3]);
            nd[1][3] = fma2(e1, *(const float2*)&c1.z,  nd[1][3]);
            nd[0][4] = fma2(e0, *(const float2*)&c2.x,  nd[0][4]);
            nd[1][4] = fma2(e1, *(const float2*)&c2.x,  nd[1][4]);
            nd[0][5] = fma2(e0, *(const float2*)&c2.z,  nd[0][5]);
            nd[1][5] = fma2(e1, *(const float2*)&c2.z,  nd[1][5]);
            nd[0][6] = fma2(e0, *(const float2*)&c3.x,  nd[0][6]);
            nd[1][6] = fma2(e1, *(const float2*)&c3.x,  nd[1][6]);
            nd[0][7] = fma2(e0, *(const float2*)&c3.z,  nd[0][7]);
            nd[1][7] = fma2(e1, *(const float2*)&c3.z,  nd[1][7]);
            nd[0][8] = fma2(e0, *(const float2*)&c4v.x, nd[0][8]);
            nd[1][8] = fma2(e1, *(const float2*)&c4v.x, nd[1][8]);
        }
    }

    // write (num,den) partials
#pragma unroll
    for (int qq = 0; qq < 2; ++qq) {
        int q = q0 + qg*2 + qq;
        float2* o = g_ND + (size_t)ks*ND_SPLIT
                         + (size_t)(b*TQ + q)*FF*HH + h;
#pragma unroll
        for (int i = 0; i < 9; ++i) {
            int f = fg*9 + i;
            o[(size_t)f*HH] = nd[qq][i];
        }
    }
}

// ---------------------------------------------------------------------------
// Kernel 3: fused epilogue (exact R15): combines k-split partials in fill.
// ---------------------------------------------------------------------------
__global__ void __launch_bounds__(128) epilogue_kernel(
        const float* __restrict__ Wc,  const float* __restrict__ bc,
        const float* __restrict__ Wo1, const float* __restrict__ bo1,
        const float* __restrict__ Wo2, const float* __restrict__ bo2,
        float* __restrict__ out) {
    int t    = threadIdx.x;
    int half = t >> 6;
    int u    = t & 63;
    int bq   = 2*blockIdx.x + half;

    __shared__ __align__(16) float hs[2*FF*HH];     // 576 floats, 2 bq
    __shared__ __align__(16) float w1s[FF*SFD + 8];

    const float2* p0 = g_ND + (size_t)(2*blockIdx.x)*FF*HH;
    const float2* p1 = p0 + ND_SPLIT;
    for (int i = t; i < 288; i += 128) {   // each i: 1 float4 per split = 2 hs
        float4 a = *(const float4*)(p0 + 2*i);
        float4 b = *(const float4*)(p1 + 2*i);
        hs[2*i]   = __fdividef(a.x + b.x, a.y + b.y);
        hs[2*i+1] = __fdividef(a.z + b.z, a.w + b.w);
    }
    if (t < 54)
        ((float4*)w1s)[t] = *(const float4*)(Wo1 + 4*t);
    __syncthreads();

    int d0 = u, d1 = u + 64, d2 = u + 128, d3 = u + 192;
    float2 wcA[HH], wcB[HH];
#pragma unroll
    for (int h = 0; h < HH; ++h) {
        wcA[h] = make_float2(Wc[h*DD + d0], Wc[h*DD + d1]);
        wcB[h] = make_float2(Wc[h*DD + d2], Wc[h*DD + d3]);
    }
    float2 bcA = make_float2(bc[d0], bc[d1]);
    float2 bcB = make_float2(bc[d2], bc[d3]);

    float2 accA[SFD], accB[SFD];
#pragma unroll
    for (int s = 0; s < SFD; ++s) { accA[s] = dup2(bo1[s]); accB[s] = dup2(bo1[s]); }

    const float* hbase = &hs[half*FF*HH];
#pragma unroll 4
    for (int f = 0; f < FF; ++f) {
        float4 h0 = *(const float4*)&hbase[f*HH];
        float4 h1 = *(const float4*)&hbase[f*HH + 4];
        float2 aA = bcA, aB = bcB;
        {
            float2 dh;
            dh = dup2(h0.x); aA = fma2(dh, wcA[0], aA); aB = fma2(dh, wcB[0], aB);
            dh = dup2(h0.y); aA = fma2(dh, wcA[1], aA); aB = fma2(dh, wcB[1], aB);
            dh = dup2(h0.z); aA = fma2(dh, wcA[2], aA); aB = fma2(dh, wcB[2], aB);
            dh = dup2(h0.w); aA = fma2(dh, wcA[3], aA); aB = fma2(dh, wcB[3], aB);
            dh = dup2(h1.x); aA = fma2(dh, wcA[4], aA); aB = fma2(dh, wcB[4], aB);
            dh = dup2(h1.y); aA = fma2(dh, wcA[5], aA); aB = fma2(dh, wcB[5], aB);
            dh = dup2(h1.z); aA = fma2(dh, wcA[6], aA); aB = fma2(dh, wcB[6], aB);
            dh = dup2(h1.w); aA = fma2(dh, wcA[7], aA); aB = fma2(dh, wcB[7], aB);
        }
        float2 latA = tanh2(aA), latB = tanh2(aB);
#pragma unroll
        for (int j = 0; j < 3; ++j) {
            float2 wpair = *(const float2*)&w1s[f*SFD + 2*j];
            float2 wlo = dup2(wpair.x), whi = dup2(wpair.y);
            accA[2*j]   = fma2(latA, wlo, accA[2*j]);
            accA[2*j+1] = fma2(latA, whi, accA[2*j+1]);
            accB[2*j]   = fma2(latB, wlo, accB[2*j]);
            accB[2*j+1] = fma2(latB, whi, accB[2*j+1]);
        }
    }

    float2 resA = make_float2(bo2[d0], bo2[d1]);
    float2 resB = make_float2(bo2[d2], bo2[d3]);
#pragma unroll
    for (int s = 0; s < SFD; ++s) {
        float2 w2 = dup2(Wo2[s]);
        resA = fma2(tanh2(accA[s]), w2, resA);
        resB = fma2(tanh2(accB[s]), w2, resB);
    }

    float* o = out + (size_t)bq*DD;
    o[d0] = resA.x; o[d1] = resA.y;
    o[d2] = resB.x; o[d3] = resB.y;
}

// ---------------------------------------------------------------------------
extern "C" void kernel_launch(void* const* d_in, const int* in_sizes, int n_in,
                              void* d_out, int out_size) {
    const float* query = (const float*)d_in[0];
    const float* key   = (const float*)d_in[1];
    const float* value = (const float*)d_in[2];
    const float* mask  = (const float*)d_in[3];
    const float* Wq    = (const float*)d_in[4];
    const float* Wk    = (const float*)d_in[5];
    const float* Wc    = (const float*)d_in[6];
    const float* bc    = (const float*)d_in[7];
    const float* Wo1   = (const float*)d_in[8];
    const float* bo1   = (const float*)d_in[9];
    const float* Wo2   = (const float*)d_in[10];
    const float* bo2   = (const float*)d_in[11];
    float* out = (float*)d_out;

    proj_kernel<<<dim3(NB*TQ/PM, DD/PN, 2), 256>>>(query, key, Wq, Wk);
    fused_attn_kernel<<<dim3(NB, HH, 8), 128>>>(value, mask);
    epilogue_kernel<<<NB*TQ/2, 128>>>(Wc, bc, Wo1, bo1, Wo2, bo2, out);
}

// round 17
// speedup vs baseline: 1.1124x; 1.1124x over previous
#include <cuda_runtime.h>

#define NB 16
#define TQ 256
#define TK 256
#define DD 256
#define FF 36
#define HH 8
#define DK 32
#define SFD 6

// Scratch (allocation-free rule: __device__ globals)
__device__ float g_Q[NB*TQ*DD];        // [b][q][h*DK+j]
__device__ float g_K[NB*TK*DD];        // [b][k][h*DK+j]
#define ND_SPLIT ((size_t)NB*TQ*FF*HH)
__device__ float2 g_ND[2*NB*TQ*FF*HH]; // [ksplit][b][q][f][h] = (num, den)

// ---------------------------------------------------------------------------
// Packed fp32x2 helpers (sm_103a: FFMA2 via PTX only)
// ---------------------------------------------------------------------------
__device__ __forceinline__ float2 fma2(float2 a, float2 b, float2 c) {
    float2 d;
    asm("fma.rn.f32x2 %0, %1, %2, %3;"
        : "=l"(reinterpret_cast<unsigned long long&>(d))
        : "l"(reinterpret_cast<unsigned long long&>(a)),
          "l"(reinterpret_cast<unsigned long long&>(b)),
          "l"(reinterpret_cast<unsigned long long&>(c)));
    return d;
}
__device__ __forceinline__ float2 dup2(float s) { return make_float2(s, s); }
__device__ __forceinline__ float2 tanh2(float2 a) {
    float2 r;
    asm("tanh.approx.f32 %0, %1;" : "=f"(r.x) : "f"(a.x));
    asm("tanh.approx.f32 %0, %1;" : "=f"(r.y) : "f"(a.y));
    return r;
}

// ---------------------------------------------------------------------------
// Kernel 1 (R15 exact, measured 31.7us): register-tiled SGEMM, tile 128x64.
// ---------------------------------------------------------------------------
#define PM 128
#define PN 64
#define PKT 16

__global__ void __launch_bounds__(256) proj_kernel(
        const float* __restrict__ query, const float* __restrict__ key,
        const float* __restrict__ Wq,    const float* __restrict__ Wk) {
    __shared__ __align__(16) float As[PKT][PM + 4];
    __shared__ __align__(16) float Bs[PKT][PN + 4];

    int n0 = blockIdx.x * PM;
    int c0 = blockIdx.y * PN;
    int which = blockIdx.z;
    const float* x = which ? key : query;
    const float* W = which ? Wk : Wq;

    int t  = threadIdx.x;
    int tm = t >> 4;
    int tn = t & 15;

    int fa_n  = t >> 1;
    int fa_k  = (t & 1) * 8;
    int fb_kk = t >> 4;
    int fb_c  = (t & 15) * 4;
    int fb_h  = (c0 + fb_c) >> 5;
    int fb_j  = (c0 + fb_c) & 31;

    float2 acc[8][2];
#pragma unroll
    for (int r = 0; r < 8; ++r) {
        acc[r][0] = make_float2(0.f, 0.f);
        acc[r][1] = make_float2(0.f, 0.f);
    }

    float4 pa0, pa1, pb;
    {
        const float* xr = x + (size_t)(n0 + fa_n)*DD + fa_k;
        pa0 = *(const float4*)(xr);
        pa1 = *(const float4*)(xr + 4);
        pb  = *(const float4*)(W + ((size_t)fb_h*DD + fb_kk)*DK + fb_j);
    }

#pragma unroll 1
    for (int kt = 0; kt < DD; kt += PKT) {
        As[fa_k+0][fa_n] = pa0.x;
        As[fa_k+1][fa_n] = pa0.y;
        As[fa_k+2][fa_n] = pa0.z;
        As[fa_k+3][fa_n] = pa0.w;
        As[fa_k+4][fa_n] = pa1.x;
        As[fa_k+5][fa_n] = pa1.y;
        As[fa_k+6][fa_n] = pa1.z;
        As[fa_k+7][fa_n] = pa1.w;
        *(float4*)(&Bs[fb_kk][fb_c]) = pb;
        __syncthreads();

        if (kt + PKT < DD) {
            const float* xr = x + (size_t)(n0 + fa_n)*DD + kt + PKT + fa_k;
            pa0 = *(const float4*)(xr);
            pa1 = *(const float4*)(xr + 4);
            pb  = *(const float4*)(W + ((size_t)fb_h*DD + kt + PKT + fb_kk)*DK + fb_j);
        }

#pragma unroll
        for (int kk = 0; kk < PKT; ++kk) {
            float4 alo = *(const float4*)&As[kk][4*tm];
            float4 ahi = *(const float4*)&As[kk][4*tm + 64];
            float4 bq  = *(const float4*)&Bs[kk][4*tn];
            float2 a[8];
            a[0] = dup2(alo.x); a[1] = dup2(alo.y);
            a[2] = dup2(alo.z); a[3] = dup2(alo.w);
            a[4] = dup2(ahi.x); a[5] = dup2(ahi.y);
            a[6] = dup2(ahi.z); a[7] = dup2(ahi.w);
            float2 bv0 = *(const float2*)&bq.x;
            float2 bv1 = *(const float2*)&bq.z;
#pragma unroll
            for (int r = 0; r < 8; ++r) {
                acc[r][0] = fma2(a[r], bv0, acc[r][0]);
                acc[r][1] = fma2(a[r], bv1, acc[r][1]);
            }
        }
        __syncthreads();
    }

    float* out = which ? g_K : g_Q;
#pragma unroll
    for (int r = 0; r < 8; ++r) {
        int n = n0 + 4*tm + (r >> 2)*64 + (r & 3);
        float4 v;
        *(float2*)&v.x = acc[r][0];
        *(float2*)&v.z = acc[r][1];
        *(float4*)(out + (size_t)n*DD + c0 + 4*tn) = v;
    }
}

// ---------------------------------------------------------------------------
// Kernel 2 (fused score+apply, split-K) with crossbar-lean layouts:
//  - Ksd non-dup [32][33]: stride 33 -> conflict-free scalar reads; dup in regs
//  - Es transposed [q][kk] stride 33: Phase A stores = conflict-free STS.32
// grid (NB, HH, 8); z = qtile*2 + ks; k range [ks*128, ks*128+128).
// ---------------------------------------------------------------------------
__global__ void __launch_bounds__(128, 5) fused_attn_kernel(
        const float* __restrict__ value, const float* __restrict__ mask) {
    int b = blockIdx.x, h = blockIdx.y;
    int q0 = (blockIdx.z >> 1) * 64;
    int ks = blockIdx.z & 1;
    int t = threadIdx.x;

    __shared__ __align__(16) float Qst[32][68];     // [j][q]
    __shared__ __align__(16) float Ks[32][33];      // [kk][j] non-dup
    __shared__ __align__(16) float Est[64][33];     // [q][kk] transposed
    __shared__ __align__(16) float Cs[32][4][20];   // [kk][fg][(mv,m)x9 + pad]

    for (int i = t; i < 64*32; i += 128) {
        int q = i >> 5, j = i & 31;
        Qst[j][q] = g_Q[(size_t)(b*TQ + q0 + q)*DD + h*DK + j];
    }

    int qg = t >> 2;            // q local = qg*2 + qq
    int fg = t & 3;             // f = fg*9 + i
    int kkA = t & 31;
    int qq4 = t >> 5;           // 16-q chunk
    // K fill: 32kk x 32j = 256 float4; i in {t, t+128}
    int kA = t >> 3,          jA = (t & 7) * 4;
    int kB = (t + 128) >> 3,  jB = ((t + 128) & 7) * 4;

    float2 nd[2][9];
#pragma unroll
    for (int qq = 0; qq < 2; ++qq)
#pragma unroll
        for (int i = 0; i < 9; ++i) nd[qq][i] = make_float2(0.f, 0.f);

    int ktEnd = ks*128 + 128;
#pragma unroll 1
    for (int kt = ks*128; kt < ktEnd; kt += 32) {
        __syncthreads();
        // K tile fill non-dup: 2 LDG.128 + 8 STS.32 (conflict-free) per thread
        {
            float4 ka = *(const float4*)&g_K[(size_t)(b*TK + kt + kA)*DD + h*DK + jA];
            float4 kb = *(const float4*)&g_K[(size_t)(b*TK + kt + kB)*DD + h*DK + jB];
            Ks[kA][jA+0] = ka.x; Ks[kA][jA+1] = ka.y;
            Ks[kA][jA+2] = ka.z; Ks[kA][jA+3] = ka.w;
            Ks[kB][jB+0] = kb.x; Ks[kB][jB+1] = kb.y;
            Ks[kB][jB+2] = kb.z; Ks[kB][jB+3] = kb.w;
        }
        // Cs fill
        for (int i = t; i < 288; i += 128) {
            int k = i / 9;
            int c4 = (i - k*9) * 4;
            size_t base = (size_t)(b*TK + kt + k)*FF + c4;
            float4 mm = *(const float4*)(mask + base);
            float4 vv = *(const float4*)(value + base);
#pragma unroll
            for (int u = 0; u < 4; ++u) {
                int f = c4 + u;
                int g = f / 9, ii = f - g*9;
                float m = (&mm.x)[u], v = (&vv.x)[u];
                Cs[k][g][2*ii]   = m * v;
                Cs[k][g][2*ii+1] = m;
            }
        }
        __syncthreads();

        // ---- Phase A: thread owns kk = kkA, computes 16 q's (qq4*16..+15)
        {
            float2 acc2[8];
#pragma unroll
            for (int p = 0; p < 8; ++p) acc2[p] = make_float2(0.f, 0.f);
#pragma unroll
            for (int jc = 0; jc < 4; ++jc) {
                float2 kr2[8];
#pragma unroll
                for (int j = 0; j < 8; ++j)
                    kr2[j] = dup2(Ks[kkA][jc*8 + j]);   // LDS.32 cf + MOV dup
#pragma unroll
                for (int j = 0; j < 8; ++j) {
                    const float4* qp = (const float4*)&Qst[jc*8 + j][qq4*16];
#pragma unroll
                    for (int c = 0; c < 4; ++c) {
                        float4 qv = qp[c];
                        acc2[2*c]   = fma2(*(const float2*)&qv.x, kr2[j], acc2[2*c]);
                        acc2[2*c+1] = fma2(*(const float2*)&qv.z, kr2[j], acc2[2*c+1]);
                    }
                }
            }
            // transposed store: 16 conflict-free STS.32 (lanes = consecutive kk)
#pragma unroll
            for (int c = 0; c < 4; ++c) {
                int qb = qq4*16 + 4*c;
                Est[qb+0][kkA] = __expf(fminf(acc2[2*c].x,   80.f));
                Est[qb+1][kkA] = __expf(fminf(acc2[2*c].y,   80.f));
                Est[qb+2][kkA] = __expf(fminf(acc2[2*c+1].x, 80.f));
                Est[qb+3][kkA] = __expf(fminf(acc2[2*c+1].y, 80.f));
            }
        }
        __syncthreads();

        // ---- Phase B: e as 2 broadcast scalars (conflict-free banks)
#pragma unroll 4
        for (int kk = 0; kk < 32; ++kk) {
            float2 e0 = dup2(Est[qg*2 + 0][kk]);
            float2 e1 = dup2(Est[qg*2 + 1][kk]);
            const float4* cp = (const float4*)&Cs[kk][fg][0];
            float4 c0 = cp[0], c1 = cp[1], c2 = cp[2], c3 = cp[3], c4v = cp[4];
            nd[0][0] = fma2(e0, *(const float2*)&c0.x,  nd[0][0]);
            nd[1][0] = fma2(e1, *(const float2*)&c0.x,  nd[1][0]);
            nd[0][1] = fma2(e0, *(const float2*)&c0.z,  nd[0][1]);
            nd[1][1] = fma2(e1, *(const float2*)&c0.z,  nd[1][1]);
            nd[0][2] = fma2(e0, *(const float2*)&c1.x,  nd[0][2]);
            nd[1][2] = fma2(e1, *(const float2*)&c1.x,  nd[1][2]);
            nd[0][3] = fma2(e0, *(const float2*)&c1.z,  nd[0][3]);
            nd[1][3] = fma2(e1, *(const float2*)&c1.z,  nd[1][3]);
            nd[0][4] = fma2(e0, *(const float2*)&c2.x,  nd[0][4]);
            nd[1][4] = fma2(e1, *(const float2*)&c2.x,  nd[1][4]);
            nd[0][5] = fma2(e0, *(const float2*)&c2.z,  nd[0][5]);
            nd[1][5] = fma2(e1, *(const float2*)&c2.z,  nd[1][5]);
            nd[0][6] = fma2(e0, *(const float2*)&c3.x,  nd[0][6]);
            nd[1][6] = fma2(e1, *(const float2*)&c3.x,  nd[1][6]);
            nd[0][7] = fma2(e0, *(const float2*)&c3.z,  nd[0][7]);
            nd[1][7] = fma2(e1, *(const float2*)&c3.z,  nd[1][7]);
            nd[0][8] = fma2(e0, *(const float2*)&c4v.x, nd[0][8]);
            nd[1][8] = fma2(e1, *(const float2*)&c4v.x, nd[1][8]);
        }
    }

    // write (num,den) partials
#pragma unroll
    for (int qq = 0; qq < 2; ++qq) {
        int q = q0 + qg*2 + qq;
        float2* o = g_ND + (size_t)ks*ND_SPLIT
                         + (size_t)(b*TQ + q)*FF*HH + h;
#pragma unroll
        for (int i = 0; i < 9; ++i) {
            int f = fg*9 + i;
            o[(size_t)f*HH] = nd[qq][i];
        }
    }
}

// ---------------------------------------------------------------------------
// Kernel 3: fused epilogue (R15 exact): combines k-split partials in fill.
// ---------------------------------------------------------------------------
__global__ void __launch_bounds__(128) epilogue_kernel(
        const float* __restrict__ Wc,  const float* __restrict__ bc,
        const float* __restrict__ Wo1, const float* __restrict__ bo1,
        const float* __restrict__ Wo2, const float* __restrict__ bo2,
        float* __restrict__ out) {
    int t    = threadIdx.x;
    int half = t >> 6;
    int u    = t & 63;
    int bq   = 2*blockIdx.x + half;

    __shared__ __align__(16) float hs[2*FF*HH];     // 576 floats, 2 bq
    __shared__ __align__(16) float w1s[FF*SFD + 8];

    const float2* p0 = g_ND + (size_t)(2*blockIdx.x)*FF*HH;
    const float2* p1 = p0 + ND_SPLIT;
    for (int i = t; i < 288; i += 128) {   // each i: 1 float4 per split = 2 hs
        float4 a = *(const float4*)(p0 + 2*i);
        float4 b = *(const float4*)(p1 + 2*i);
        hs[2*i]   = __fdividef(a.x + b.x, a.y + b.y);
        hs[2*i+1] = __fdividef(a.z + b.z, a.w + b.w);
    }
    if (t < 54)
        ((float4*)w1s)[t] = *(const float4*)(Wo1 + 4*t);
    __syncthreads();

    int d0 = u, d1 = u + 64, d2 = u + 128, d3 = u + 192;
    float2 wcA[HH], wcB[HH];
#pragma unroll
    for (int h = 0; h < HH; ++h) {
        wcA[h] = make_float2(Wc[h*DD + d0], Wc[h*DD + d1]);
        wcB[h] = make_float2(Wc[h*DD + d2], Wc[h*DD + d3]);
    }
    float2 bcA = make_float2(bc[d0], bc[d1]);
    float2 bcB = make_float2(bc[d2], bc[d3]);

    float2 accA[SFD], accB[SFD];
#pragma unroll
    for (int s = 0; s < SFD; ++s) { accA[s] = dup2(bo1[s]); accB[s] = dup2(bo1[s]); }

    const float* hbase = &hs[half*FF*HH];
#pragma unroll 4
    for (int f = 0; f < FF; ++f) {
        float4 h0 = *(const float4*)&hbase[f*HH];
        float4 h1 = *(const float4*)&hbase[f*HH + 4];
        float2 aA = bcA, aB = bcB;
        {
            float2 dh;
            dh = dup2(h0.x); aA = fma2(dh, wcA[0], aA); aB = fma2(dh, wcB[0], aB);
            dh = dup2(h0.y); aA = fma2(dh, wcA[1], aA); aB = fma2(dh, wcB[1], aB);
            dh = dup2(h0.z); aA = fma2(dh, wcA[2], aA); aB = fma2(dh, wcB[2], aB);
            dh = dup2(h0.w); aA = fma2(dh, wcA[3], aA); aB = fma2(dh, wcB[3], aB);
            dh = dup2(h1.x); aA = fma2(dh, wcA[4], aA); aB = fma2(dh, wcB[4], aB);
            dh = dup2(h1.y); aA = fma2(dh, wcA[5], aA); aB = fma2(dh, wcB[5], aB);
            dh = dup2(h1.z); aA = fma2(dh, wcA[6], aA); aB = fma2(dh, wcB[6], aB);
            dh = dup2(h1.w); aA = fma2(dh, wcA[7], aA); aB = fma2(dh, wcB[7], aB);
        }
        float2 latA = tanh2(aA), latB = tanh2(aB);
#pragma unroll
        for (int j = 0; j < 3; ++j) {
            float2 wpair = *(const float2*)&w1s[f*SFD + 2*j];
            float2 wlo = dup2(wpair.x), whi = dup2(wpair.y);
            accA[2*j]   = fma2(latA, wlo, accA[2*j]);
            accA[2*j+1] = fma2(latA, whi, accA[2*j+1]);
            accB[2*j]   = fma2(latB, wlo, accB[2*j]);
            accB[2*j+1] = fma2(latB, whi, accB[2*j+1]);
        }
    }

    float2 resA = make_float2(bo2[d0], bo2[d1]);
    float2 resB = make_float2(bo2[d2], bo2[d3]);
#pragma unroll
    for (int s = 0; s < SFD; ++s) {
        float2 w2 = dup2(Wo2[s]);
        resA = fma2(tanh2(accA[s]), w2, resA);
        resB = fma2(tanh2(accB[s]), w2, resB);
    }

    float* o = out + (size_t)bq*DD;
    o[d0] = resA.x; o[d1] = resA.y;
    o[d2] = resB.x; o[d3] = resB.y;
}

// ---------------------------------------------------------------------------
extern "C" void kernel_launch(void* const* d_in, const int* in_sizes, int n_in,
                              void* d_out, int out_size) {
    const float* query = (const float*)d_in[0];
    const float* key   = (const float*)d_in[1];
    const float* value = (const float*)d_in[2];
    const float* mask  = (const float*)d_in[3];
    const float* Wq    = (const float*)d_in[4];
    const float* Wk    = (const float*)d_in[5];
    const float* Wc    = (const float*)d_in[6];
    const float* bc    = (const float*)d_in[7];
    const float* Wo1   = (const float*)d_in[8];
    const float* bo1   = (const float*)d_in[9];
    const float* Wo2   = (const float*)d_in[10];
    const float* bo2   = (const float*)d_in[11];
    float* out = (float*)d_out;

    proj_kernel<<<dim3(NB*TQ/PM, DD/PN, 2), 256>>>(query, key, Wq, Wk);
    fused_attn_kernel<<<dim3(NB, HH, 8), 128>>>(value, mask);
    epilogue_kernel<<<NB*TQ/2, 128>>>(Wc, bc, Wo1, bo1, Wo2, bo2, out);
}